// round 5
// baseline (speedup 1.0000x reference)
#include <cuda_runtime.h>
#include <math.h>

#define FULLMASK 0xFFFFFFFFu

// ---------------- static device scratch (no allocation) ----------------
__device__ float d_La[1024];     // alpha logits (batch-constant)
__device__ float d_c1[128];      // baseline_b @ W1b[:1024] + b1b
__device__ float d_p1[2][8192];  // layer-1 partials (64 chunks x 128) x {alpha, beta}
__device__ float d_h2[64];       // alpha hidden-2

__device__ __forceinline__ float leaky(float x) { return x >= 0.f ? x : 0.01f * x; }

// order-preserving float -> unsigned key (monotone bijection on non-NaN)
__device__ __forceinline__ unsigned f2ord(float f) {
    unsigned u = __float_as_uint(f);
    return u ^ (unsigned)(((int)u >> 31) | 0x80000000);
}

static __device__ __forceinline__ unsigned long long pack2(float x, float y) {
    unsigned long long r;
    asm("mov.b64 %0, {%1, %2};" : "=l"(r) : "f"(x), "f"(y));
    return r;
}
static __device__ __forceinline__ void unpack2(unsigned long long v, float& x, float& y) {
    asm("mov.b64 {%0, %1}, %2;" : "=f"(x), "=f"(y) : "l"(v));
}
static __device__ __forceinline__ unsigned long long fma2(unsigned long long a,
                                                          unsigned long long b,
                                                          unsigned long long c) {
    unsigned long long d;
    asm("fma.rn.f32x2 %0, %1, %2, %3;" : "=l"(d) : "l"(a), "l"(b), "l"(c));
    return d;
}

// sorted top-4 insert (strict >, preserves lowest-j among equals)
__device__ __forceinline__ void ins4(unsigned x, int j,
                                     unsigned& m0, unsigned& m1, unsigned& m2, unsigned& m3,
                                     int& i0, int& i1, int& i2, int& i3) {
    if (x > m3) {
        if (x > m1) {
            if (x > m0) { m3 = m2; i3 = i2; m2 = m1; i2 = i1; m1 = m0; i1 = i0; m0 = x; i0 = j; }
            else        { m3 = m2; i3 = i2; m2 = m1; i2 = i1; m1 = x; i1 = j; }
        } else {
            if (x > m2) { m3 = m2; i3 = i2; m2 = x; i2 = j; }
            else        { m3 = x; i3 = j; }
        }
    }
}

// ---------------- warp top-32-of-1024 on ordered uint keys ----------------
// Lane owns v[j] <-> global index (j>>2)*128 + lane*4 + (j&3)   (float4 layout).
// All real keys >= 0x00800000, so 0 is a safe "consumed" sentinel.
// One REDUX.MAX per round; per-lane lazy top-4 cache -> masked rescan is ~never.
template <bool WANT_IDX>
__device__ __forceinline__ unsigned warp_select32(const unsigned* v, int lane, int* my_gidx) {
    unsigned m0 = 0, m1 = 0, m2 = 0, m3 = 0;
    int i0 = 0, i1 = 0, i2 = 0, i3 = 0;
#pragma unroll
    for (int j = 0; j < 32; j++) ins4(v[j], j, m0, m1, m2, m3, i0, i1, i2, i3);
    unsigned sel = 0;
#pragma unroll 1
    for (int k = 0; k < 32; k++) {
        unsigned best = __reduce_max_sync(FULLMASK, m0);
        unsigned bal = __ballot_sync(FULLMASK, m0 == best);
        int wl = __ffs(bal) - 1;
        if (WANT_IDX) {
            int wj = __shfl_sync(FULLMASK, i0, wl);
            if (lane == k) *my_gidx = (wj >> 2) * 128 + wl * 4 + (wj & 3);
        }
        if (lane == wl) {
            sel |= 1u << i0;
            m0 = m1; i0 = i1; m1 = m2; i1 = i2; m2 = m3; i2 = i3; m3 = 0; i3 = 0;
            if (m0 == 0) {  // all 4 cached consumed (P ~ 0.3%/row): masked rescan
#pragma unroll
                for (int j = 0; j < 32; j++)
                    if (!((sel >> j) & 1)) ins4(v[j], j, m0, m1, m2, m3, i0, i1, i2, i3);
            }
        }
    }
    return sel;
}

// ---------------- kp1: layer-1 partials for alpha-h1 and beta-c1 (64 blocks) ----------------
__global__ __launch_bounds__(256) void kp1(const float* __restrict__ ba,
                                           const float* __restrict__ W1a,
                                           const float* __restrict__ bb,
                                           const float* __restrict__ W1b) {
    int t = threadIdx.x;
    int o = t & 127, sel = t >> 7;
    const float* W = sel ? W1b : W1a;
    const float* xv = sel ? bb : ba;
    int i0 = blockIdx.x * 16;
    float p = 0.f;
#pragma unroll
    for (int k = 0; k < 16; k++) p += xv[i0 + k] * W[(i0 + k) * 128 + o];
    d_p1[sel][blockIdx.x * 128 + o] = p;
}

// ---------------- kp2: reduce partials, layer-2 alpha (1 block) ----------------
__global__ __launch_bounds__(256) void kp2(const float* __restrict__ b1a,
                                           const float* __restrict__ b1b,
                                           const float* __restrict__ W2a,
                                           const float* __restrict__ b2a) {
    __shared__ float h1[128];
    __shared__ float red[256];
    int t = threadIdx.x;
    int o = t & 127, sel = t >> 7;
    const float* p = d_p1[sel];
    float s = 0.f;
#pragma unroll 8
    for (int k = 0; k < 64; k++) s += p[k * 128 + o];
    if (sel == 0) h1[o] = leaky(b1a[o] + s);
    else d_c1[o] = b1b[o] + s;
    __syncthreads();
    int o2 = t & 63, c2 = t >> 6;
    float q = 0.f;
#pragma unroll
    for (int k = 0; k < 32; k++) {
        int i = c2 * 32 + k;
        q += h1[i] * W2a[i * 64 + o2];
    }
    red[t] = q;
    __syncthreads();
    if (t < 64)
        d_h2[t] = leaky(b2a[t] + red[t] + red[64 + t] + red[128 + t] + red[192 + t]);
}

// ---------------- kp3: layer-3 alpha -> La (8 blocks) ----------------
__global__ __launch_bounds__(128) void kp3(const float* __restrict__ W3a,
                                           const float* __restrict__ b3a,
                                           const float* __restrict__ ba) {
    __shared__ float h2s[64];
    int t = threadIdx.x;
    if (t < 64) h2s[t] = d_h2[t];
    __syncthreads();
    int o = blockIdx.x * 128 + t;
    float s = 0.f;
#pragma unroll
    for (int i = 0; i < 64; i++) s += h2s[i] * W3a[i * 1024 + o];
    d_La[o] = s + b3a[o] + ba[o];
}

// ---------------- kmain: fused alpha-select + ctx + beta MLP + beta-select ----------------
// 16 rows/block, 256 threads, 3 CTAs/SM.
// Shared overlay (float offsets), total 17408 floats = 69632 B:
//   [0,1024)      h2t            (live: layer2 -> layer3)
//   [1024,5120)   W1b ctx-slice  (live: load -> layer1)
//   [5120,13312)  W2b            (live: load -> layer2)
//   [13312,14336) La_s           (live: load -> alpha)       \ overlap OK:
//   [13312,15360) h1s            (live: layer1 -> layer2)    / h1s written after alpha
//   [15360,15872) ctx_s          (live: alpha -> layer1)
//   [1024,17408)  lg             (live: layer3 -> beta select; everything above
//                                 except h2t is dead by then)
constexpr int F_H2T = 0;
constexpr int F_W1  = 1024;
constexpr int F_W2  = 5120;
constexpr int F_LA  = 13312;
constexpr int F_H1  = 13312;
constexpr int F_CTX = 15360;
constexpr int F_LG  = 1024;
constexpr int SMEM_FLOATS = 17408;  // 69632 bytes

__global__ __launch_bounds__(256, 3) void kmain(
        const float* __restrict__ g_alpha, const float* __restrict__ g_beta,
        const float* __restrict__ Wc, const float* __restrict__ bc,
        const float* __restrict__ W1b, const float* __restrict__ W2b,
        const float* __restrict__ b2b, const float* __restrict__ W3b,
        const float* __restrict__ b3b, const float* __restrict__ baseline_b,
        float* __restrict__ out, int B) {
    extern __shared__ float sm[];
    float* h2t   = sm + F_H2T;
    float* w1s   = sm + F_W1;
    float* w2s   = sm + F_W2;
    float* La_s  = sm + F_LA;
    float* h1s   = sm + F_H1;
    float* ctx_s = sm + F_CTX;
    float* lg    = sm + F_LG;
    int t = threadIdx.x;
    int row0 = blockIdx.x * 16;
    if (row0 >= B) return;

    for (int x = t; x < 1024; x += 256) La_s[x] = d_La[x];
    for (int x = t; x < 4096; x += 256) w1s[x] = W1b[131072 + x];  // rows 1024..1055
    for (int x = t; x < 8192; x += 256) w2s[x] = W2b[x];
    __syncthreads();

    int w = t >> 5, lane = t & 31;
    // ---- alpha: 2 rows per warp ----
#pragma unroll 1
    for (int rr = w * 2; rr < w * 2 + 2; rr++) {
        int row = row0 + rr;
        if (row >= B) { ctx_s[rr * 32 + lane] = 0.f; continue; }
        const float* g = g_alpha + (size_t)row * 1024;
        unsigned v[32];
#pragma unroll
        for (int j4 = 0; j4 < 8; j4++) {
            float4 gv = __ldg((const float4*)(g + j4 * 128 + lane * 4));
            float4 lv = *(const float4*)(La_s + j4 * 128 + lane * 4);
            v[j4 * 4 + 0] = f2ord(lv.x + gv.x);
            v[j4 * 4 + 1] = f2ord(lv.y + gv.y);
            v[j4 * 4 + 2] = f2ord(lv.z + gv.z);
            v[j4 * 4 + 3] = f2ord(lv.w + gv.w);
        }
        int gidx = 0;
        unsigned sel = warp_select32<true>(v, lane, &gidx);
        float* o = out + (size_t)row * 2048;
#pragma unroll
        for (int j4 = 0; j4 < 8; j4++) {
            float4 ov;
            ov.x = ((sel >> (j4 * 4 + 0)) & 1) ? 1.f : 0.f;
            ov.y = ((sel >> (j4 * 4 + 1)) & 1) ? 1.f : 0.f;
            ov.z = ((sel >> (j4 * 4 + 2)) & 1) ? 1.f : 0.f;
            ov.w = ((sel >> (j4 * 4 + 3)) & 1) ? 1.f : 0.f;
            *(float4*)(o + j4 * 128 + lane * 4) = ov;
        }
        // ctx = bc + sum of selected Wc rows
        float acc = __ldg(bc + lane);
#pragma unroll
        for (int k = 0; k < 32; k++) {
            int idx = __shfl_sync(FULLMASK, gidx, k);
            acc += __ldg(Wc + (size_t)idx * 32 + lane);
        }
        ctx_s[rr * 32 + lane] = acc;
    }
    __syncthreads();  // alpha done: La_s dead; h1s may now overwrite it

    int r = t >> 4, s = t & 15;
    // ---- layer 1 (W1b ctx-slice from smem; base_b part folded into d_c1) ----
    {
        float acc[8];
#pragma unroll
        for (int k = 0; k < 8; k++) acc[k] = d_c1[s + 16 * k];
        for (int i = 0; i < 32; i++) {
            float cv = ctx_s[r * 32 + i];
#pragma unroll
            for (int k = 0; k < 8; k++) acc[k] += cv * w1s[i * 128 + s + 16 * k];
        }
#pragma unroll
        for (int k = 0; k < 8; k++) h1s[r * 128 + s + 16 * k] = leaky(acc[k]);
    }
    __syncthreads();
    // ---- layer 2 (W2b from smem) ----
    {
        float acc[4];
#pragma unroll
        for (int k = 0; k < 4; k++) acc[k] = __ldg(&b2b[s + 16 * k]);
        for (int i = 0; i < 128; i++) {
            float hv = h1s[r * 128 + i];
#pragma unroll
            for (int k = 0; k < 4; k++) acc[k] += hv * w2s[i * 64 + s + 16 * k];
        }
#pragma unroll
        for (int k = 0; k < 4; k++) h2t[(s + 16 * k) * 16 + r] = leaky(acc[k]);
    }
    __syncthreads();  // h2t ready; all of the pool except h2t is dead -> lg
    // ---- layer 3: two passes of 8 rows (acc regs halved -> 3 CTAs/SM) ----
    {
        int o0 = t * 4;
        float bq[4];
#pragma unroll
        for (int q = 0; q < 4; q++) bq[q] = __ldg(&b3b[o0 + q]) + __ldg(&baseline_b[o0 + q]);
#pragma unroll 1
        for (int pass = 0; pass < 2; pass++) {
            unsigned long long acc[16];
#pragma unroll
            for (int z = 0; z < 16; z++) acc[z] = 0ull;
#pragma unroll 4
            for (int i = 0; i < 64; i++) {
                float4 wv = __ldg((const float4*)(W3b + i * 1024 + o0));
                unsigned long long w0 = pack2(wv.x, wv.x);
                unsigned long long w1 = pack2(wv.y, wv.y);
                unsigned long long w2p = pack2(wv.z, wv.z);
                unsigned long long w3 = pack2(wv.w, wv.w);
                const float2* hp = (const float2*)(h2t + i * 16) + pass * 4;
#pragma unroll
                for (int rp = 0; rp < 4; rp++) {
                    float2 h = hp[rp];
                    unsigned long long hh = pack2(h.x, h.y);
                    acc[rp * 4 + 0] = fma2(w0, hh, acc[rp * 4 + 0]);
                    acc[rp * 4 + 1] = fma2(w1, hh, acc[rp * 4 + 1]);
                    acc[rp * 4 + 2] = fma2(w2p, hh, acc[rp * 4 + 2]);
                    acc[rp * 4 + 3] = fma2(w3, hh, acc[rp * 4 + 3]);
                }
            }
#pragma unroll
            for (int rp = 0; rp < 4; rp++) {
                float lo0, hi0, lo1, hi1, lo2, hi2, lo3, hi3;
                unpack2(acc[rp * 4 + 0], lo0, hi0);
                unpack2(acc[rp * 4 + 1], lo1, hi1);
                unpack2(acc[rp * 4 + 2], lo2, hi2);
                unpack2(acc[rp * 4 + 3], lo3, hi3);
                int rowl = pass * 8 + rp * 2;
                *(float4*)(lg + rowl * 1024 + o0) =
                    make_float4(lo0 + bq[0], lo1 + bq[1], lo2 + bq[2], lo3 + bq[3]);
                *(float4*)(lg + (rowl + 1) * 1024 + o0) =
                    make_float4(hi0 + bq[0], hi1 + bq[1], hi2 + bq[2], hi3 + bq[3]);
            }
        }
    }
    __syncthreads();
    // ---- beta selection: 2 rows per warp ----
#pragma unroll 1
    for (int rr = w * 2; rr < w * 2 + 2; rr++) {
        int row = row0 + rr;
        if (row >= B) continue;
        const float* g = g_beta + (size_t)row * 1024;
        unsigned v[32];
#pragma unroll
        for (int j4 = 0; j4 < 8; j4++) {
            float4 gv = __ldg((const float4*)(g + j4 * 128 + lane * 4));
            float4 lv = *(const float4*)(lg + rr * 1024 + j4 * 128 + lane * 4);
            v[j4 * 4 + 0] = f2ord(lv.x + gv.x);
            v[j4 * 4 + 1] = f2ord(lv.y + gv.y);
            v[j4 * 4 + 2] = f2ord(lv.z + gv.z);
            v[j4 * 4 + 3] = f2ord(lv.w + gv.w);
        }
        int dummy;
        unsigned sel = warp_select32<false>(v, lane, &dummy);
        float* o = out + (size_t)row * 2048 + 1024;
#pragma unroll
        for (int j4 = 0; j4 < 8; j4++) {
            float4 ov;
            ov.x = ((sel >> (j4 * 4 + 0)) & 1) ? 1.f : 0.f;
            ov.y = ((sel >> (j4 * 4 + 1)) & 1) ? 1.f : 0.f;
            ov.z = ((sel >> (j4 * 4 + 2)) & 1) ? 1.f : 0.f;
            ov.w = ((sel >> (j4 * 4 + 3)) & 1) ? 1.f : 0.f;
            *(float4*)(o + j4 * 128 + lane * 4) = ov;
        }
    }
}

// ---------------- launcher ----------------
extern "C" void kernel_launch(void* const* d_in, const int* in_sizes, int n_in,
                              void* d_out, int out_size) {
    const float* baseline_a = (const float*)d_in[0];
    const float* W1a = (const float*)d_in[1];
    const float* b1a = (const float*)d_in[2];
    const float* W2a = (const float*)d_in[3];
    const float* b2a = (const float*)d_in[4];
    const float* W3a = (const float*)d_in[5];
    const float* b3a = (const float*)d_in[6];
    const float* baseline_b = (const float*)d_in[7];
    const float* Wc  = (const float*)d_in[8];
    const float* bc  = (const float*)d_in[9];
    const float* W1b = (const float*)d_in[10];
    const float* b1b = (const float*)d_in[11];
    const float* W2b = (const float*)d_in[12];
    const float* b2b = (const float*)d_in[13];
    const float* W3b = (const float*)d_in[14];
    const float* b3b = (const float*)d_in[15];
    const float* g_alpha = (const float*)d_in[16];
    const float* g_beta  = (const float*)d_in[17];
    float* out = (float*)d_out;

    int B = in_sizes[16] / 1024;
    if (B <= 0) return;

    cudaFuncSetAttribute(kmain, cudaFuncAttributeMaxDynamicSharedMemorySize,
                         SMEM_FLOATS * sizeof(float));

    kp1<<<64, 256>>>(baseline_a, W1a, baseline_b, W1b);
    kp2<<<1, 256>>>(b1a, b1b, W2a, b2a);
    kp3<<<8, 128>>>(W3a, b3a, baseline_a);
    kmain<<<(B + 15) / 16, 256, SMEM_FLOATS * sizeof(float)>>>(
        g_alpha, g_beta, Wc, bc, W1b, W2b, b2b, W3b, b3b, baseline_b, out, B);
}

// round 6
// speedup vs baseline: 1.0176x; 1.0176x over previous
#include <cuda_runtime.h>
#include <math.h>

#define FULLMASK 0xFFFFFFFFu

// ---------------- static device scratch (no allocation) ----------------
__device__ __align__(16) float d_La[1024];     // alpha logits (batch-constant)
__device__ __align__(16) float d_c1[128];      // baseline_b @ W1b[:1024] + b1b
__device__ __align__(16) float d_p1[2][8192];  // layer-1 partials
__device__ __align__(16) float d_h2[64];       // alpha hidden-2

__device__ __forceinline__ float leaky(float x) { return x >= 0.f ? x : 0.01f * x; }

// order-preserving float -> unsigned key (monotone bijection on non-NaN)
__device__ __forceinline__ unsigned f2ord(float f) {
    unsigned u = __float_as_uint(f);
    return u ^ (unsigned)(((int)u >> 31) | 0x80000000);
}

static __device__ __forceinline__ unsigned long long pack2(float x, float y) {
    unsigned long long r;
    asm("mov.b64 %0, {%1, %2};" : "=l"(r) : "f"(x), "f"(y));
    return r;
}
static __device__ __forceinline__ void unpack2(unsigned long long v, float& x, float& y) {
    asm("mov.b64 {%0, %1}, %2;" : "=f"(x), "=f"(y) : "l"(v));
}
static __device__ __forceinline__ unsigned long long fma2(unsigned long long a,
                                                          unsigned long long b,
                                                          unsigned long long c) {
    unsigned long long d;
    asm("fma.rn.f32x2 %0, %1, %2, %3;" : "=l"(d) : "l"(a), "l"(b), "l"(c));
    return d;
}

// sorted top-4 insert (strict >, preserves lowest-j among equals)
__device__ __forceinline__ void ins4(unsigned x, int j,
                                     unsigned& m0, unsigned& m1, unsigned& m2, unsigned& m3,
                                     int& i0, int& i1, int& i2, int& i3) {
    if (x > m3) {
        if (x > m1) {
            if (x > m0) { m3 = m2; i3 = i2; m2 = m1; i2 = i1; m1 = m0; i1 = i0; m0 = x; i0 = j; }
            else        { m3 = m2; i3 = i2; m2 = m1; i2 = i1; m1 = x; i1 = j; }
        } else {
            if (x > m2) { m3 = m2; i3 = i2; m2 = x; i2 = j; }
            else        { m3 = x; i3 = j; }
        }
    }
}

// ---------------- warp top-32-of-1024 on ordered uint keys ----------------
// Lane owns v[j] <-> global index (j>>2)*128 + lane*4 + (j&3)   (float4 layout).
// All real keys >= 0x00800000, so 0 is a safe "consumed" sentinel.
template <bool WANT_IDX>
__device__ __forceinline__ unsigned warp_select32(const unsigned* v, int lane, int* my_gidx) {
    unsigned m0 = 0, m1 = 0, m2 = 0, m3 = 0;
    int i0 = 0, i1 = 0, i2 = 0, i3 = 0;
#pragma unroll
    for (int j = 0; j < 32; j++) ins4(v[j], j, m0, m1, m2, m3, i0, i1, i2, i3);
    unsigned sel = 0;
#pragma unroll 1
    for (int k = 0; k < 32; k++) {
        unsigned best = __reduce_max_sync(FULLMASK, m0);
        unsigned bal = __ballot_sync(FULLMASK, m0 == best);
        int wl = __ffs(bal) - 1;
        if (WANT_IDX) {
            int wj = __shfl_sync(FULLMASK, i0, wl);
            if (lane == k) *my_gidx = (wj >> 2) * 128 + wl * 4 + (wj & 3);
        }
        if (lane == wl) {
            sel |= 1u << i0;
            m0 = m1; i0 = i1; m1 = m2; i1 = i2; m2 = m3; i2 = i3; m3 = 0; i3 = 0;
            if (m0 == 0) {  // all 4 cached consumed (rare): masked rescan
#pragma unroll
                for (int j = 0; j < 32; j++)
                    if (!((sel >> j) & 1)) ins4(v[j], j, m0, m1, m2, m3, i0, i1, i2, i3);
            }
        }
    }
    return sel;
}

// ---------------- kp1: layer-1 partials for alpha-h1 and beta-c1 (64 blocks) ----------------
__global__ __launch_bounds__(256) void kp1(const float* __restrict__ ba,
                                           const float* __restrict__ W1a,
                                           const float* __restrict__ bb,
                                           const float* __restrict__ W1b) {
    int t = threadIdx.x;
    int o = t & 127, sel = t >> 7;
    const float* W = sel ? W1b : W1a;
    const float* xv = sel ? bb : ba;
    int i0 = blockIdx.x * 16;
    float p = 0.f;
#pragma unroll
    for (int k = 0; k < 16; k++) p += xv[i0 + k] * W[(i0 + k) * 128 + o];
    d_p1[sel][blockIdx.x * 128 + o] = p;
}

// ---------------- kp2: reduce partials, layer-2 alpha (1 block) ----------------
__global__ __launch_bounds__(256) void kp2(const float* __restrict__ b1a,
                                           const float* __restrict__ b1b,
                                           const float* __restrict__ W2a,
                                           const float* __restrict__ b2a) {
    __shared__ float h1[128];
    __shared__ float red[256];
    int t = threadIdx.x;
    int o = t & 127, sel = t >> 7;
    const float* p = d_p1[sel];
    float s = 0.f;
#pragma unroll 8
    for (int k = 0; k < 64; k++) s += p[k * 128 + o];
    if (sel == 0) h1[o] = leaky(b1a[o] + s);
    else d_c1[o] = b1b[o] + s;
    __syncthreads();
    int o2 = t & 63, c2 = t >> 6;
    float q = 0.f;
#pragma unroll
    for (int k = 0; k < 32; k++) {
        int i = c2 * 32 + k;
        q += h1[i] * W2a[i * 64 + o2];
    }
    red[t] = q;
    __syncthreads();
    if (t < 64)
        d_h2[t] = leaky(b2a[t] + red[t] + red[64 + t] + red[128 + t] + red[192 + t]);
}

// ---------------- kp3: layer-3 alpha -> La (8 blocks) ----------------
__global__ __launch_bounds__(128) void kp3(const float* __restrict__ W3a,
                                           const float* __restrict__ b3a,
                                           const float* __restrict__ ba) {
    __shared__ float h2s[64];
    int t = threadIdx.x;
    if (t < 64) h2s[t] = d_h2[t];
    __syncthreads();
    int o = blockIdx.x * 128 + t;
    float s = 0.f;
#pragma unroll
    for (int i = 0; i < 64; i++) s += h2s[i] * W3a[i * 1024 + o];
    d_La[o] = s + b3a[o] + ba[o];
}

// ---------------- kmain: fused alpha-select + ctx + beta MLP + beta-select ----------------
// 16 rows/block, 256 threads, 2 CTAs/SM (occupancy shown non-binding in R5).
// Shared overlay (float offsets), total 17408 floats = 69632 B:
//   [0,1024)      h2t            (live: layer2 -> layer3)
//   [1024,5120)   W1b ctx-slice  (live: load -> layer1)
//   [5120,13312)  W2b            (live: load -> layer2)
//   [13312,14336) La_s           (live: load -> alpha)
//   [13312,15360) h1s            (live: layer1 -> layer2)  (overwrites La_s: OK)
//   [15360,15872) ctx_s          (live: alpha -> layer1)
//   [1024,17408)  lg             (live: layer3 -> beta select)
constexpr int F_H2T = 0;
constexpr int F_W1  = 1024;
constexpr int F_W2  = 5120;
constexpr int F_LA  = 13312;
constexpr int F_H1  = 13312;
constexpr int F_CTX = 15360;
constexpr int F_LG  = 1024;
constexpr int SMEM_FLOATS = 17408;  // 69632 bytes

__global__ __launch_bounds__(256, 2) void kmain(
        const float* __restrict__ g_alpha, const float* __restrict__ g_beta,
        const float* __restrict__ Wc, const float* __restrict__ bc,
        const float* __restrict__ W1b, const float* __restrict__ W2b,
        const float* __restrict__ b2b, const float* __restrict__ W3b,
        const float* __restrict__ b3b, const float* __restrict__ baseline_b,
        float* __restrict__ out, int B) {
    extern __shared__ float sm[];
    float* h2t   = sm + F_H2T;
    float* w1s   = sm + F_W1;
    float* w2s   = sm + F_W2;
    float* La_s  = sm + F_LA;
    float* h1s   = sm + F_H1;
    float* ctx_s = sm + F_CTX;
    float* lg    = sm + F_LG;
    int t = threadIdx.x;
    int row0 = blockIdx.x * 16;
    if (row0 >= B) return;

    // vectorized fills
    ((float4*)La_s)[t] = __ldg((const float4*)d_La + t);
#pragma unroll
    for (int x = 0; x < 4; x++)
        ((float4*)w1s)[x * 256 + t] = __ldg((const float4*)(W1b + 131072) + x * 256 + t);
#pragma unroll
    for (int x = 0; x < 8; x++)
        ((float4*)w2s)[x * 256 + t] = __ldg((const float4*)W2b + x * 256 + t);
    __syncthreads();

    int w = t >> 5, lane = t & 31;
    // ---- alpha: 2 rows per warp ----
#pragma unroll 1
    for (int rr = w * 2; rr < w * 2 + 2; rr++) {
        int row = row0 + rr;
        if (row >= B) { ctx_s[rr * 32 + lane] = 0.f; continue; }
        const float* g = g_alpha + (size_t)row * 1024;
        unsigned v[32];
#pragma unroll
        for (int j4 = 0; j4 < 8; j4++) {
            float4 gv = __ldg((const float4*)(g + j4 * 128 + lane * 4));
            float4 lv = *(const float4*)(La_s + j4 * 128 + lane * 4);
            v[j4 * 4 + 0] = f2ord(lv.x + gv.x);
            v[j4 * 4 + 1] = f2ord(lv.y + gv.y);
            v[j4 * 4 + 2] = f2ord(lv.z + gv.z);
            v[j4 * 4 + 3] = f2ord(lv.w + gv.w);
        }
        int gidx = 0;
        unsigned sel = warp_select32<true>(v, lane, &gidx);
        float* o = out + (size_t)row * 2048;
#pragma unroll
        for (int j4 = 0; j4 < 8; j4++) {
            float4 ov;
            ov.x = ((sel >> (j4 * 4 + 0)) & 1) ? 1.f : 0.f;
            ov.y = ((sel >> (j4 * 4 + 1)) & 1) ? 1.f : 0.f;
            ov.z = ((sel >> (j4 * 4 + 2)) & 1) ? 1.f : 0.f;
            ov.w = ((sel >> (j4 * 4 + 3)) & 1) ? 1.f : 0.f;
            *(float4*)(o + j4 * 128 + lane * 4) = ov;
        }
        // ctx = bc + sum of selected Wc rows
        float acc = __ldg(bc + lane);
#pragma unroll
        for (int k = 0; k < 32; k++) {
            int idx = __shfl_sync(FULLMASK, gidx, k);
            acc += __ldg(Wc + (size_t)idx * 32 + lane);
        }
        ctx_s[rr * 32 + lane] = acc;
    }
    __syncthreads();  // alpha done: La_s dead; h1s may now overwrite it

    int r = t >> 4, s = t & 15;
    // ---- layer 1: thread owns 8 contiguous outputs (LDS.128 weight loads) ----
    {
        float4 a0 = __ldg((const float4*)(d_c1 + s * 8));
        float4 a1 = __ldg((const float4*)(d_c1 + s * 8 + 4));
        for (int i = 0; i < 32; i++) {
            float cv = ctx_s[r * 32 + i];
            float4 w0 = *(const float4*)(w1s + i * 128 + s * 8);
            float4 w1 = *(const float4*)(w1s + i * 128 + s * 8 + 4);
            a0.x += cv * w0.x; a0.y += cv * w0.y; a0.z += cv * w0.z; a0.w += cv * w0.w;
            a1.x += cv * w1.x; a1.y += cv * w1.y; a1.z += cv * w1.z; a1.w += cv * w1.w;
        }
        *(float4*)(h1s + r * 128 + s * 8) =
            make_float4(leaky(a0.x), leaky(a0.y), leaky(a0.z), leaky(a0.w));
        *(float4*)(h1s + r * 128 + s * 8 + 4) =
            make_float4(leaky(a1.x), leaky(a1.y), leaky(a1.z), leaky(a1.w));
    }
    __syncthreads();
    // ---- layer 2: thread owns 4 contiguous outputs (LDS.128 weight loads) ----
    {
        float4 a = __ldg((const float4*)(b2b + s * 4));
        for (int i = 0; i < 128; i++) {
            float hv = h1s[r * 128 + i];
            float4 wv = *(const float4*)(w2s + i * 64 + s * 4);
            a.x += hv * wv.x; a.y += hv * wv.y; a.z += hv * wv.z; a.w += hv * wv.w;
        }
        h2t[(s * 4 + 0) * 16 + r] = leaky(a.x);
        h2t[(s * 4 + 1) * 16 + r] = leaky(a.y);
        h2t[(s * 4 + 2) * 16 + r] = leaky(a.z);
        h2t[(s * 4 + 3) * 16 + r] = leaky(a.w);
    }
    __syncthreads();  // h2t ready; rest of the pool is dead -> lg
    // ---- layer 3: one pass, thread owns 4 outputs x 16 rows (f32x2) ----
    {
        int o0 = t * 4;
        unsigned long long acc[32];
#pragma unroll
        for (int z = 0; z < 32; z++) acc[z] = 0ull;
#pragma unroll 4
        for (int i = 0; i < 64; i++) {
            float4 wv = __ldg((const float4*)(W3b + i * 1024 + o0));
            unsigned long long w0 = pack2(wv.x, wv.x);
            unsigned long long w1 = pack2(wv.y, wv.y);
            unsigned long long w2p = pack2(wv.z, wv.z);
            unsigned long long w3 = pack2(wv.w, wv.w);
            float4 hA = *(const float4*)(h2t + i * 16);
            float4 hB = *(const float4*)(h2t + i * 16 + 4);
            float4 hC = *(const float4*)(h2t + i * 16 + 8);
            float4 hD = *(const float4*)(h2t + i * 16 + 12);
            unsigned long long hh[8];
            hh[0] = pack2(hA.x, hA.y); hh[1] = pack2(hA.z, hA.w);
            hh[2] = pack2(hB.x, hB.y); hh[3] = pack2(hB.z, hB.w);
            hh[4] = pack2(hC.x, hC.y); hh[5] = pack2(hC.z, hC.w);
            hh[6] = pack2(hD.x, hD.y); hh[7] = pack2(hD.z, hD.w);
#pragma unroll
            for (int rp = 0; rp < 8; rp++) {
                acc[rp * 4 + 0] = fma2(w0, hh[rp], acc[rp * 4 + 0]);
                acc[rp * 4 + 1] = fma2(w1, hh[rp], acc[rp * 4 + 1]);
                acc[rp * 4 + 2] = fma2(w2p, hh[rp], acc[rp * 4 + 2]);
                acc[rp * 4 + 3] = fma2(w3, hh[rp], acc[rp * 4 + 3]);
            }
        }
        float bq[4];
#pragma unroll
        for (int q = 0; q < 4; q++) bq[q] = __ldg(&b3b[o0 + q]) + __ldg(&baseline_b[o0 + q]);
#pragma unroll
        for (int rp = 0; rp < 8; rp++) {
            float lo0, hi0, lo1, hi1, lo2, hi2, lo3, hi3;
            unpack2(acc[rp * 4 + 0], lo0, hi0);
            unpack2(acc[rp * 4 + 1], lo1, hi1);
            unpack2(acc[rp * 4 + 2], lo2, hi2);
            unpack2(acc[rp * 4 + 3], lo3, hi3);
            *(float4*)(lg + (rp * 2) * 1024 + o0) =
                make_float4(lo0 + bq[0], lo1 + bq[1], lo2 + bq[2], lo3 + bq[3]);
            *(float4*)(lg + (rp * 2 + 1) * 1024 + o0) =
                make_float4(hi0 + bq[0], hi1 + bq[1], hi2 + bq[2], hi3 + bq[3]);
        }
    }
    __syncthreads();
    // ---- beta selection: 2 rows per warp ----
#pragma unroll 1
    for (int rr = w * 2; rr < w * 2 + 2; rr++) {
        int row = row0 + rr;
        if (row >= B) continue;
        const float* g = g_beta + (size_t)row * 1024;
        unsigned v[32];
#pragma unroll
        for (int j4 = 0; j4 < 8; j4++) {
            float4 gv = __ldg((const float4*)(g + j4 * 128 + lane * 4));
            float4 lv = *(const float4*)(lg + rr * 1024 + j4 * 128 + lane * 4);
            v[j4 * 4 + 0] = f2ord(lv.x + gv.x);
            v[j4 * 4 + 1] = f2ord(lv.y + gv.y);
            v[j4 * 4 + 2] = f2ord(lv.z + gv.z);
            v[j4 * 4 + 3] = f2ord(lv.w + gv.w);
        }
        int dummy;
        unsigned sel = warp_select32<false>(v, lane, &dummy);
        float* o = out + (size_t)row * 2048 + 1024;
#pragma unroll
        for (int j4 = 0; j4 < 8; j4++) {
            float4 ov;
            ov.x = ((sel >> (j4 * 4 + 0)) & 1) ? 1.f : 0.f;
            ov.y = ((sel >> (j4 * 4 + 1)) & 1) ? 1.f : 0.f;
            ov.z = ((sel >> (j4 * 4 + 2)) & 1) ? 1.f : 0.f;
            ov.w = ((sel >> (j4 * 4 + 3)) & 1) ? 1.f : 0.f;
            *(float4*)(o + j4 * 128 + lane * 4) = ov;
        }
    }
}

// ---------------- launcher ----------------
extern "C" void kernel_launch(void* const* d_in, const int* in_sizes, int n_in,
                              void* d_out, int out_size) {
    const float* baseline_a = (const float*)d_in[0];
    const float* W1a = (const float*)d_in[1];
    const float* b1a = (const float*)d_in[2];
    const float* W2a = (const float*)d_in[3];
    const float* b2a = (const float*)d_in[4];
    const float* W3a = (const float*)d_in[5];
    const float* b3a = (const float*)d_in[6];
    const float* baseline_b = (const float*)d_in[7];
    const float* Wc  = (const float*)d_in[8];
    const float* bc  = (const float*)d_in[9];
    const float* W1b = (const float*)d_in[10];
    const float* b1b = (const float*)d_in[11];
    const float* W2b = (const float*)d_in[12];
    const float* b2b = (const float*)d_in[13];
    const float* W3b = (const float*)d_in[14];
    const float* b3b = (const float*)d_in[15];
    const float* g_alpha = (const float*)d_in[16];
    const float* g_beta  = (const float*)d_in[17];
    float* out = (float*)d_out;

    int B = in_sizes[16] / 1024;
    if (B <= 0) return;

    cudaFuncSetAttribute(kmain, cudaFuncAttributeMaxDynamicSharedMemorySize,
                         SMEM_FLOATS * sizeof(float));

    kp1<<<64, 256>>>(baseline_a, W1a, baseline_b, W1b);
    kp2<<<1, 256>>>(b1a, b1b, W2a, b2a);
    kp3<<<8, 128>>>(W3a, b3a, baseline_a);
    kmain<<<(B + 15) / 16, 256, SMEM_FLOATS * sizeof(float)>>>(
        g_alpha, g_beta, Wc, bc, W1b, W2b, b2b, W3b, b3b, baseline_b, out, B);
}

// round 7
// speedup vs baseline: 1.0721x; 1.0535x over previous
#include <cuda_runtime.h>
#include <math.h>

#define FULLMASK 0xFFFFFFFFu

// ---------------- static device scratch (no allocation) ----------------
__device__ __align__(16) float d_La[1024];     // alpha logits (batch-constant)
__device__ __align__(16) float d_c1[128];      // baseline_b @ W1b[:1024] + b1b
__device__ __align__(16) float d_p1[2][8192];  // layer-1 partials

__device__ __forceinline__ float leaky(float x) { return x >= 0.f ? x : 0.01f * x; }

// order-preserving float -> unsigned key (monotone bijection on non-NaN)
__device__ __forceinline__ unsigned f2ord(float f) {
    unsigned u = __float_as_uint(f);
    return u ^ (unsigned)(((int)u >> 31) | 0x80000000);
}

static __device__ __forceinline__ unsigned long long pack2(float x, float y) {
    unsigned long long r;
    asm("mov.b64 %0, {%1, %2};" : "=l"(r) : "f"(x), "f"(y));
    return r;
}
static __device__ __forceinline__ void unpack2(unsigned long long v, float& x, float& y) {
    asm("mov.b64 {%0, %1}, %2;" : "=f"(x), "=f"(y) : "l"(v));
}
static __device__ __forceinline__ unsigned long long fma2(unsigned long long a,
                                                          unsigned long long b,
                                                          unsigned long long c) {
    unsigned long long d;
    asm("fma.rn.f32x2 %0, %1, %2, %3;" : "=l"(d) : "l"(a), "l"(b), "l"(c));
    return d;
}

// sorted top-4 insert (strict >, preserves lowest-j among equals)
__device__ __forceinline__ void ins4(unsigned x, int j,
                                     unsigned& m0, unsigned& m1, unsigned& m2, unsigned& m3,
                                     int& i0, int& i1, int& i2, int& i3) {
    if (x > m3) {
        if (x > m1) {
            if (x > m0) { m3 = m2; i3 = i2; m2 = m1; i2 = i1; m1 = m0; i1 = i0; m0 = x; i0 = j; }
            else        { m3 = m2; i3 = i2; m2 = m1; i2 = i1; m1 = x; i1 = j; }
        } else {
            if (x > m2) { m3 = m2; i3 = i2; m2 = x; i2 = j; }
            else        { m3 = x; i3 = j; }
        }
    }
}

// ---------------- single-row warp top-32 (partial-tile fallback) ----------------
template <bool WANT_IDX>
__device__ __forceinline__ unsigned warp_select32(const unsigned* v, int lane, int* my_gidx) {
    unsigned m0 = 0, m1 = 0, m2 = 0, m3 = 0;
    int i0 = 0, i1 = 0, i2 = 0, i3 = 0;
#pragma unroll
    for (int j = 0; j < 32; j++) ins4(v[j], j, m0, m1, m2, m3, i0, i1, i2, i3);
    unsigned sel = 0;
#pragma unroll 1
    for (int k = 0; k < 32; k++) {
        unsigned best = __reduce_max_sync(FULLMASK, m0);
        unsigned bal = __ballot_sync(FULLMASK, m0 == best);
        int wl = __ffs(bal) - 1;
        if (WANT_IDX) {
            int wj = __shfl_sync(FULLMASK, i0, wl);
            if (lane == k) *my_gidx = (wj >> 2) * 128 + wl * 4 + (wj & 3);
        }
        if (lane == wl) {
            sel |= 1u << i0;
            m0 = m1; i0 = i1; m1 = m2; i1 = i2; m2 = m3; i2 = i3; m3 = 0; i3 = 0;
            if (m0 == 0) {
#pragma unroll
                for (int j = 0; j < 32; j++)
                    if (!((sel >> j) & 1)) ins4(v[j], j, m0, m1, m2, m3, i0, i1, i2, i3);
            }
        }
    }
    return sel;
}

// ---------------- paired warp top-32: two independent rows, chains pipelined ----------------
template <bool WANT_IDX>
__device__ __forceinline__ void warp_select32_pair(
        const unsigned* va, const unsigned* vb, int lane,
        unsigned& selA, unsigned& selB, int* gidxA, int* gidxB) {
    unsigned a0 = 0, a1 = 0, a2 = 0, a3 = 0;
    int ai0 = 0, ai1 = 0, ai2 = 0, ai3 = 0;
    unsigned b0 = 0, b1 = 0, b2 = 0, b3 = 0;
    int bi0 = 0, bi1 = 0, bi2 = 0, bi3 = 0;
#pragma unroll
    for (int j = 0; j < 32; j++) {
        ins4(va[j], j, a0, a1, a2, a3, ai0, ai1, ai2, ai3);
        ins4(vb[j], j, b0, b1, b2, b3, bi0, bi1, bi2, bi3);
    }
    selA = 0; selB = 0;
#pragma unroll 1
    for (int k = 0; k < 32; k++) {
        unsigned bestA = __reduce_max_sync(FULLMASK, a0);
        unsigned bestB = __reduce_max_sync(FULLMASK, b0);
        unsigned balA = __ballot_sync(FULLMASK, a0 == bestA);
        unsigned balB = __ballot_sync(FULLMASK, b0 == bestB);
        int wlA = __ffs(balA) - 1;
        int wlB = __ffs(balB) - 1;
        if (WANT_IDX) {
            int wjA = __shfl_sync(FULLMASK, ai0, wlA);
            int wjB = __shfl_sync(FULLMASK, bi0, wlB);
            if (lane == k) {
                *gidxA = (wjA >> 2) * 128 + wlA * 4 + (wjA & 3);
                *gidxB = (wjB >> 2) * 128 + wlB * 4 + (wjB & 3);
            }
        }
        if (lane == wlA) {
            selA |= 1u << ai0;
            a0 = a1; ai0 = ai1; a1 = a2; ai1 = ai2; a2 = a3; ai2 = ai3; a3 = 0; ai3 = 0;
            if (a0 == 0) {
#pragma unroll
                for (int j = 0; j < 32; j++)
                    if (!((selA >> j) & 1)) ins4(va[j], j, a0, a1, a2, a3, ai0, ai1, ai2, ai3);
            }
        }
        if (lane == wlB) {
            selB |= 1u << bi0;
            b0 = b1; bi0 = bi1; b1 = b2; bi1 = bi2; b2 = b3; bi2 = bi3; b3 = 0; bi3 = 0;
            if (b0 == 0) {
#pragma unroll
                for (int j = 0; j < 32; j++)
                    if (!((selB >> j) & 1)) ins4(vb[j], j, b0, b1, b2, b3, bi0, bi1, bi2, bi3);
            }
        }
    }
}

// ---------------- kp1: layer-1 partials for alpha-h1 and beta-c1 (64 blocks) ----------------
__global__ __launch_bounds__(256) void kp1(const float* __restrict__ ba,
                                           const float* __restrict__ W1a,
                                           const float* __restrict__ bb,
                                           const float* __restrict__ W1b) {
    int t = threadIdx.x;
    int o = t & 127, sel = t >> 7;
    const float* W = sel ? W1b : W1a;
    const float* xv = sel ? bb : ba;
    int i0 = blockIdx.x * 16;
    float p = 0.f;
#pragma unroll
    for (int k = 0; k < 16; k++) p += xv[i0 + k] * W[(i0 + k) * 128 + o];
    d_p1[sel][blockIdx.x * 128 + o] = p;
}

// ---------------- kpa: reduce partials + alpha layers 2-3 (1 block x 1024) ----------------
__global__ __launch_bounds__(1024) void kpa(const float* __restrict__ b1a,
                                            const float* __restrict__ b1b,
                                            const float* __restrict__ W2a,
                                            const float* __restrict__ b2a,
                                            const float* __restrict__ W3a,
                                            const float* __restrict__ b3a,
                                            const float* __restrict__ ba) {
    __shared__ float h1[128];
    __shared__ float h2s[64];
    __shared__ float red[256];
    int t = threadIdx.x;
    if (t < 256) {
        int o = t & 127, sel = t >> 7;
        const float* p = d_p1[sel];
        float s = 0.f;
#pragma unroll 8
        for (int k = 0; k < 64; k++) s += p[k * 128 + o];
        if (sel == 0) h1[o] = leaky(b1a[o] + s);
        else d_c1[o] = b1b[o] + s;
    }
    __syncthreads();
    if (t < 256) {
        int o2 = t & 63, c2 = t >> 6;
        float q = 0.f;
#pragma unroll
        for (int k = 0; k < 32; k++) {
            int i = c2 * 32 + k;
            q += h1[i] * W2a[i * 64 + o2];
        }
        red[t] = q;
    }
    __syncthreads();
    if (t < 64)
        h2s[t] = leaky(b2a[t] + red[t] + red[64 + t] + red[128 + t] + red[192 + t]);
    __syncthreads();
    float s = 0.f;
#pragma unroll
    for (int i = 0; i < 64; i++) s += h2s[i] * W3a[i * 1024 + t];
    d_La[t] = s + b3a[t] + ba[t];
}

// ---------------- kmain: fused alpha-select + ctx + beta MLP + beta-select ----------------
// 16 rows/block, 256 threads, 2 CTAs/SM. Shared overlay (float offsets):
//   [0,1024)      h2t   | [1024,5120) W1b-slice | [5120,13312) W2b
//   [13312,14336) La_s  | [13312,15360) h1s (after alpha) | [15360,15872) ctx_s
//   [1024,17408)  lg (after layer 2)
constexpr int F_H2T = 0;
constexpr int F_W1  = 1024;
constexpr int F_W2  = 5120;
constexpr int F_LA  = 13312;
constexpr int F_H1  = 13312;
constexpr int F_CTX = 15360;
constexpr int F_LG  = 1024;
constexpr int SMEM_FLOATS = 17408;  // 69632 bytes

__global__ __launch_bounds__(256, 2) void kmain(
        const float* __restrict__ g_alpha, const float* __restrict__ g_beta,
        const float* __restrict__ Wc, const float* __restrict__ bc,
        const float* __restrict__ W1b, const float* __restrict__ W2b,
        const float* __restrict__ b2b, const float* __restrict__ W3b,
        const float* __restrict__ b3b, const float* __restrict__ baseline_b,
        float* __restrict__ out, int B) {
    extern __shared__ float sm[];
    float* h2t   = sm + F_H2T;
    float* w1s   = sm + F_W1;
    float* w2s   = sm + F_W2;
    float* La_s  = sm + F_LA;
    float* h1s   = sm + F_H1;
    float* ctx_s = sm + F_CTX;
    float* lg    = sm + F_LG;
    int t = threadIdx.x;
    int row0 = blockIdx.x * 16;
    if (row0 >= B) return;
    bool full = (row0 + 16 <= B);

    // vectorized fills
    ((float4*)La_s)[t] = __ldg((const float4*)d_La + t);
#pragma unroll
    for (int x = 0; x < 4; x++)
        ((float4*)w1s)[x * 256 + t] = __ldg((const float4*)(W1b + 131072) + x * 256 + t);
#pragma unroll
    for (int x = 0; x < 8; x++)
        ((float4*)w2s)[x * 256 + t] = __ldg((const float4*)W2b + x * 256 + t);
    __syncthreads();

    int w = t >> 5, lane = t & 31;
    // ---- alpha: 2 rows per warp, selections interleaved ----
    if (full) {
        int rA = row0 + w * 2, rB = rA + 1;
        const float* gA = g_alpha + (size_t)rA * 1024;
        const float* gB = g_alpha + (size_t)rB * 1024;
        unsigned va[32], vb[32];
#pragma unroll
        for (int j4 = 0; j4 < 8; j4++) {
            float4 lv = *(const float4*)(La_s + j4 * 128 + lane * 4);
            float4 ga = __ldg((const float4*)(gA + j4 * 128 + lane * 4));
            float4 gb = __ldg((const float4*)(gB + j4 * 128 + lane * 4));
            va[j4 * 4 + 0] = f2ord(lv.x + ga.x);
            va[j4 * 4 + 1] = f2ord(lv.y + ga.y);
            va[j4 * 4 + 2] = f2ord(lv.z + ga.z);
            va[j4 * 4 + 3] = f2ord(lv.w + ga.w);
            vb[j4 * 4 + 0] = f2ord(lv.x + gb.x);
            vb[j4 * 4 + 1] = f2ord(lv.y + gb.y);
            vb[j4 * 4 + 2] = f2ord(lv.z + gb.z);
            vb[j4 * 4 + 3] = f2ord(lv.w + gb.w);
        }
        int gidxA = 0, gidxB = 0;
        unsigned selA, selB;
        warp_select32_pair<true>(va, vb, lane, selA, selB, &gidxA, &gidxB);
        float* oA = out + (size_t)rA * 2048;
        float* oB = out + (size_t)rB * 2048;
#pragma unroll
        for (int j4 = 0; j4 < 8; j4++) {
            float4 ov;
            ov.x = ((selA >> (j4 * 4 + 0)) & 1) ? 1.f : 0.f;
            ov.y = ((selA >> (j4 * 4 + 1)) & 1) ? 1.f : 0.f;
            ov.z = ((selA >> (j4 * 4 + 2)) & 1) ? 1.f : 0.f;
            ov.w = ((selA >> (j4 * 4 + 3)) & 1) ? 1.f : 0.f;
            *(float4*)(oA + j4 * 128 + lane * 4) = ov;
            ov.x = ((selB >> (j4 * 4 + 0)) & 1) ? 1.f : 0.f;
            ov.y = ((selB >> (j4 * 4 + 1)) & 1) ? 1.f : 0.f;
            ov.z = ((selB >> (j4 * 4 + 2)) & 1) ? 1.f : 0.f;
            ov.w = ((selB >> (j4 * 4 + 3)) & 1) ? 1.f : 0.f;
            *(float4*)(oB + j4 * 128 + lane * 4) = ov;
        }
        float accA = __ldg(bc + lane), accB = accA;
#pragma unroll
        for (int k = 0; k < 32; k++) {
            int iA = __shfl_sync(FULLMASK, gidxA, k);
            int iB = __shfl_sync(FULLMASK, gidxB, k);
            accA += __ldg(Wc + (size_t)iA * 32 + lane);
            accB += __ldg(Wc + (size_t)iB * 32 + lane);
        }
        ctx_s[(w * 2) * 32 + lane] = accA;
        ctx_s[(w * 2 + 1) * 32 + lane] = accB;
    } else {
#pragma unroll 1
        for (int rr = w * 2; rr < w * 2 + 2; rr++) {
            int row = row0 + rr;
            if (row >= B) { ctx_s[rr * 32 + lane] = 0.f; continue; }
            const float* g = g_alpha + (size_t)row * 1024;
            unsigned v[32];
#pragma unroll
            for (int j4 = 0; j4 < 8; j4++) {
                float4 gv = __ldg((const float4*)(g + j4 * 128 + lane * 4));
                float4 lv = *(const float4*)(La_s + j4 * 128 + lane * 4);
                v[j4 * 4 + 0] = f2ord(lv.x + gv.x);
                v[j4 * 4 + 1] = f2ord(lv.y + gv.y);
                v[j4 * 4 + 2] = f2ord(lv.z + gv.z);
                v[j4 * 4 + 3] = f2ord(lv.w + gv.w);
            }
            int gidx = 0;
            unsigned sel = warp_select32<true>(v, lane, &gidx);
            float* o = out + (size_t)row * 2048;
#pragma unroll
            for (int j4 = 0; j4 < 8; j4++) {
                float4 ov;
                ov.x = ((sel >> (j4 * 4 + 0)) & 1) ? 1.f : 0.f;
                ov.y = ((sel >> (j4 * 4 + 1)) & 1) ? 1.f : 0.f;
                ov.z = ((sel >> (j4 * 4 + 2)) & 1) ? 1.f : 0.f;
                ov.w = ((sel >> (j4 * 4 + 3)) & 1) ? 1.f : 0.f;
                *(float4*)(o + j4 * 128 + lane * 4) = ov;
            }
            float acc = __ldg(bc + lane);
#pragma unroll
            for (int k = 0; k < 32; k++) {
                int idx = __shfl_sync(FULLMASK, gidx, k);
                acc += __ldg(Wc + (size_t)idx * 32 + lane);
            }
            ctx_s[rr * 32 + lane] = acc;
        }
    }
    __syncthreads();  // alpha done: La_s dead; h1s may overwrite it

    int r = t >> 4, s = t & 15;
    // ---- layer 1: thread owns 8 contiguous outputs; ctx via float4 ----
    {
        float4 a0 = __ldg((const float4*)(d_c1 + s * 8));
        float4 a1 = __ldg((const float4*)(d_c1 + s * 8 + 4));
        const float* cr = ctx_s + r * 32;
#pragma unroll
        for (int i4 = 0; i4 < 32; i4 += 4) {
            float4 cv = *(const float4*)(cr + i4);
#pragma unroll
            for (int u = 0; u < 4; u++) {
                float c = (u == 0) ? cv.x : (u == 1) ? cv.y : (u == 2) ? cv.z : cv.w;
                float4 w0 = *(const float4*)(w1s + (i4 + u) * 128 + s * 8);
                float4 w1 = *(const float4*)(w1s + (i4 + u) * 128 + s * 8 + 4);
                a0.x += c * w0.x; a0.y += c * w0.y; a0.z += c * w0.z; a0.w += c * w0.w;
                a1.x += c * w1.x; a1.y += c * w1.y; a1.z += c * w1.z; a1.w += c * w1.w;
            }
        }
        *(float4*)(h1s + r * 128 + s * 8) =
            make_float4(leaky(a0.x), leaky(a0.y), leaky(a0.z), leaky(a0.w));
        *(float4*)(h1s + r * 128 + s * 8 + 4) =
            make_float4(leaky(a1.x), leaky(a1.y), leaky(a1.z), leaky(a1.w));
    }
    __syncthreads();
    // ---- layer 2: thread owns 4 contiguous outputs; h1 via float4 ----
    {
        float4 a = __ldg((const float4*)(b2b + s * 4));
        const float* h1r = h1s + r * 128;
#pragma unroll 4
        for (int i4 = 0; i4 < 128; i4 += 4) {
            float4 hv = *(const float4*)(h1r + i4);
#pragma unroll
            for (int u = 0; u < 4; u++) {
                float h = (u == 0) ? hv.x : (u == 1) ? hv.y : (u == 2) ? hv.z : hv.w;
                float4 wv = *(const float4*)(w2s + (i4 + u) * 64 + s * 4);
                a.x += h * wv.x; a.y += h * wv.y; a.z += h * wv.z; a.w += h * wv.w;
            }
        }
        h2t[(s * 4 + 0) * 16 + r] = leaky(a.x);
        h2t[(s * 4 + 1) * 16 + r] = leaky(a.y);
        h2t[(s * 4 + 2) * 16 + r] = leaky(a.z);
        h2t[(s * 4 + 3) * 16 + r] = leaky(a.w);
    }
    __syncthreads();  // h2t ready; rest of the pool dead -> lg
    // ---- layer 3: thread owns 4 outputs x 16 rows (f32x2); h2t via ulonglong2 ----
    {
        int o0 = t * 4;
        unsigned long long acc[32];
#pragma unroll
        for (int z = 0; z < 32; z++) acc[z] = 0ull;
#pragma unroll 4
        for (int i = 0; i < 64; i++) {
            float4 wv = __ldg((const float4*)(W3b + i * 1024 + o0));
            unsigned long long w0 = pack2(wv.x, wv.x);
            unsigned long long w1 = pack2(wv.y, wv.y);
            unsigned long long w2p = pack2(wv.z, wv.z);
            unsigned long long w3 = pack2(wv.w, wv.w);
            ulonglong2 p0 = *(const ulonglong2*)(h2t + i * 16);
            ulonglong2 p1 = *(const ulonglong2*)(h2t + i * 16 + 4);
            ulonglong2 p2 = *(const ulonglong2*)(h2t + i * 16 + 8);
            ulonglong2 p3 = *(const ulonglong2*)(h2t + i * 16 + 12);
            unsigned long long hh[8] = {p0.x, p0.y, p1.x, p1.y, p2.x, p2.y, p3.x, p3.y};
#pragma unroll
            for (int rp = 0; rp < 8; rp++) {
                acc[rp * 4 + 0] = fma2(w0, hh[rp], acc[rp * 4 + 0]);
                acc[rp * 4 + 1] = fma2(w1, hh[rp], acc[rp * 4 + 1]);
                acc[rp * 4 + 2] = fma2(w2p, hh[rp], acc[rp * 4 + 2]);
                acc[rp * 4 + 3] = fma2(w3, hh[rp], acc[rp * 4 + 3]);
            }
        }
        float bq[4];
#pragma unroll
        for (int q = 0; q < 4; q++) bq[q] = __ldg(&b3b[o0 + q]) + __ldg(&baseline_b[o0 + q]);
#pragma unroll
        for (int rp = 0; rp < 8; rp++) {
            float lo0, hi0, lo1, hi1, lo2, hi2, lo3, hi3;
            unpack2(acc[rp * 4 + 0], lo0, hi0);
            unpack2(acc[rp * 4 + 1], lo1, hi1);
            unpack2(acc[rp * 4 + 2], lo2, hi2);
            unpack2(acc[rp * 4 + 3], lo3, hi3);
            *(float4*)(lg + (rp * 2) * 1024 + o0) =
                make_float4(lo0 + bq[0], lo1 + bq[1], lo2 + bq[2], lo3 + bq[3]);
            *(float4*)(lg + (rp * 2 + 1) * 1024 + o0) =
                make_float4(hi0 + bq[0], hi1 + bq[1], hi2 + bq[2], hi3 + bq[3]);
        }
    }
    __syncthreads();
    // ---- beta selection: 2 rows per warp, interleaved ----
    if (full) {
        int rA = row0 + w * 2, rB = rA + 1;
        const float* gA = g_beta + (size_t)rA * 1024;
        const float* gB = g_beta + (size_t)rB * 1024;
        unsigned va[32], vb[32];
#pragma unroll
        for (int j4 = 0; j4 < 8; j4++) {
            float4 la = *(const float4*)(lg + (w * 2) * 1024 + j4 * 128 + lane * 4);
            float4 lb = *(const float4*)(lg + (w * 2 + 1) * 1024 + j4 * 128 + lane * 4);
            float4 ga = __ldg((const float4*)(gA + j4 * 128 + lane * 4));
            float4 gb = __ldg((const float4*)(gB + j4 * 128 + lane * 4));
            va[j4 * 4 + 0] = f2ord(la.x + ga.x);
            va[j4 * 4 + 1] = f2ord(la.y + ga.y);
            va[j4 * 4 + 2] = f2ord(la.z + ga.z);
            va[j4 * 4 + 3] = f2ord(la.w + ga.w);
            vb[j4 * 4 + 0] = f2ord(lb.x + gb.x);
            vb[j4 * 4 + 1] = f2ord(lb.y + gb.y);
            vb[j4 * 4 + 2] = f2ord(lb.z + gb.z);
            vb[j4 * 4 + 3] = f2ord(lb.w + gb.w);
        }
        unsigned selA, selB;
        int du0, du1;
        warp_select32_pair<false>(va, vb, lane, selA, selB, &du0, &du1);
        float* oA = out + (size_t)rA * 2048 + 1024;
        float* oB = out + (size_t)rB * 2048 + 1024;
#pragma unroll
        for (int j4 = 0; j4 < 8; j4++) {
            float4 ov;
            ov.x = ((selA >> (j4 * 4 + 0)) & 1) ? 1.f : 0.f;
            ov.y = ((selA >> (j4 * 4 + 1)) & 1) ? 1.f : 0.f;
            ov.z = ((selA >> (j4 * 4 + 2)) & 1) ? 1.f : 0.f;
            ov.w = ((selA >> (j4 * 4 + 3)) & 1) ? 1.f : 0.f;
            *(float4*)(oA + j4 * 128 + lane * 4) = ov;
            ov.x = ((selB >> (j4 * 4 + 0)) & 1) ? 1.f : 0.f;
            ov.y = ((selB >> (j4 * 4 + 1)) & 1) ? 1.f : 0.f;
            ov.z = ((selB >> (j4 * 4 + 2)) & 1) ? 1.f : 0.f;
            ov.w = ((selB >> (j4 * 4 + 3)) & 1) ? 1.f : 0.f;
            *(float4*)(oB + j4 * 128 + lane * 4) = ov;
        }
    } else {
#pragma unroll 1
        for (int rr = w * 2; rr < w * 2 + 2; rr++) {
            int row = row0 + rr;
            if (row >= B) continue;
            const float* g = g_beta + (size_t)row * 1024;
            unsigned v[32];
#pragma unroll
            for (int j4 = 0; j4 < 8; j4++) {
                float4 gv = __ldg((const float4*)(g + j4 * 128 + lane * 4));
                float4 lv = *(const float4*)(lg + rr * 1024 + j4 * 128 + lane * 4);
                v[j4 * 4 + 0] = f2ord(lv.x + gv.x);
                v[j4 * 4 + 1] = f2ord(lv.y + gv.y);
                v[j4 * 4 + 2] = f2ord(lv.z + gv.z);
                v[j4 * 4 + 3] = f2ord(lv.w + gv.w);
            }
            int dummy;
            unsigned sel = warp_select32<false>(v, lane, &dummy);
            float* o = out + (size_t)row * 2048 + 1024;
#pragma unroll
            for (int j4 = 0; j4 < 8; j4++) {
                float4 ov;
                ov.x = ((sel >> (j4 * 4 + 0)) & 1) ? 1.f : 0.f;
                ov.y = ((sel >> (j4 * 4 + 1)) & 1) ? 1.f : 0.f;
                ov.z = ((sel >> (j4 * 4 + 2)) & 1) ? 1.f : 0.f;
                ov.w = ((sel >> (j4 * 4 + 3)) & 1) ? 1.f : 0.f;
                *(float4*)(o + j4 * 128 + lane * 4) = ov;
            }
        }
    }
}

// ---------------- launcher ----------------
extern "C" void kernel_launch(void* const* d_in, const int* in_sizes, int n_in,
                              void* d_out, int out_size) {
    const float* baseline_a = (const float*)d_in[0];
    const float* W1a = (const float*)d_in[1];
    const float* b1a = (const float*)d_in[2];
    const float* W2a = (const float*)d_in[3];
    const float* b2a = (const float*)d_in[4];
    const float* W3a = (const float*)d_in[5];
    const float* b3a = (const float*)d_in[6];
    const float* baseline_b = (const float*)d_in[7];
    const float* Wc  = (const float*)d_in[8];
    const float* bc  = (const float*)d_in[9];
    const float* W1b = (const float*)d_in[10];
    const float* b1b = (const float*)d_in[11];
    const float* W2b = (const float*)d_in[12];
    const float* b2b = (const float*)d_in[13];
    const float* W3b = (const float*)d_in[14];
    const float* b3b = (const float*)d_in[15];
    const float* g_alpha = (const float*)d_in[16];
    const float* g_beta  = (const float*)d_in[17];
    float* out = (float*)d_out;

    int B = in_sizes[16] / 1024;
    if (B <= 0) return;

    cudaFuncSetAttribute(kmain, cudaFuncAttributeMaxDynamicSharedMemorySize,
                         SMEM_FLOATS * sizeof(float));

    kp1<<<64, 256>>>(baseline_a, W1a, baseline_b, W1b);
    kpa<<<1, 1024>>>(b1a, b1b, W2a, b2a, W3a, b3a, baseline_a);
    kmain<<<(B + 15) / 16, 256, SMEM_FLOATS * sizeof(float)>>>(
        g_alpha, g_beta, Wc, bc, W1b, W2b, b2b, W3b, b3b, baseline_b, out, B);
}

// round 8
// speedup vs baseline: 1.0882x; 1.0151x over previous
#include <cuda_runtime.h>
#include <math.h>

#define FULLMASK 0xFFFFFFFFu

// ---------------- static device scratch (no allocation) ----------------
__device__ __align__(16) float d_La[1024];     // alpha logits (batch-constant)
__device__ __align__(16) float d_c1[128];      // baseline_b @ W1b[:1024] + b1b
__device__ __align__(16) float d_p1[2][8192];  // layer-1 partials

__device__ __forceinline__ float leaky(float x) { return x >= 0.f ? x : 0.01f * x; }

// order-preserving float -> unsigned key (monotone bijection on non-NaN)
__device__ __forceinline__ unsigned f2ord(float f) {
    unsigned u = __float_as_uint(f);
    return u ^ (unsigned)(((int)u >> 31) | 0x80000000);
}

static __device__ __forceinline__ unsigned long long pack2(float x, float y) {
    unsigned long long r;
    asm("mov.b64 %0, {%1, %2};" : "=l"(r) : "f"(x), "f"(y));
    return r;
}
static __device__ __forceinline__ void unpack2(unsigned long long v, float& x, float& y) {
    asm("mov.b64 {%0, %1}, %2;" : "=f"(x), "=f"(y) : "l"(v));
}
static __device__ __forceinline__ unsigned long long fma2(unsigned long long a,
                                                          unsigned long long b,
                                                          unsigned long long c) {
    unsigned long long d;
    asm("fma.rn.f32x2 %0, %1, %2, %3;" : "=l"(d) : "l"(a), "l"(b), "l"(c));
    return d;
}

// sorted top-4 insert (strict >, preserves lowest-j among equals)
__device__ __forceinline__ void ins4(unsigned x, int j,
                                     unsigned& m0, unsigned& m1, unsigned& m2, unsigned& m3,
                                     int& i0, int& i1, int& i2, int& i3) {
    if (x > m3) {
        if (x > m1) {
            if (x > m0) { m3 = m2; i3 = i2; m2 = m1; i2 = i1; m1 = m0; i1 = i0; m0 = x; i0 = j; }
            else        { m3 = m2; i3 = i2; m2 = m1; i2 = i1; m1 = x; i1 = j; }
        } else {
            if (x > m2) { m3 = m2; i3 = i2; m2 = x; i2 = j; }
            else        { m3 = x; i3 = j; }
        }
    }
}

// ---------------- warp top-32-of-1024 on ordered uint keys ----------------
// Lane owns v[j] <-> global index (j>>2)*128 + lane*4 + (j&3)   (float4 layout).
// All real keys >= 0x00800000, so 0 is a safe "consumed" sentinel.
template <bool WANT_IDX>
__device__ __forceinline__ unsigned warp_select32(const unsigned* v, int lane, int* my_gidx) {
    unsigned m0 = 0, m1 = 0, m2 = 0, m3 = 0;
    int i0 = 0, i1 = 0, i2 = 0, i3 = 0;
#pragma unroll
    for (int j = 0; j < 32; j++) ins4(v[j], j, m0, m1, m2, m3, i0, i1, i2, i3);
    unsigned sel = 0;
#pragma unroll 1
    for (int k = 0; k < 32; k++) {
        unsigned best = __reduce_max_sync(FULLMASK, m0);
        unsigned bal = __ballot_sync(FULLMASK, m0 == best);
        int wl = __ffs(bal) - 1;
        if (WANT_IDX) {
            int wj = __shfl_sync(FULLMASK, i0, wl);
            if (lane == k) *my_gidx = (wj >> 2) * 128 + wl * 4 + (wj & 3);
        }
        if (lane == wl) {
            sel |= 1u << i0;
            m0 = m1; i0 = i1; m1 = m2; i1 = i2; m2 = m3; i2 = i3; m3 = 0; i3 = 0;
            if (m0 == 0) {  // all 4 cached consumed (rare): masked rescan
#pragma unroll
                for (int j = 0; j < 32; j++)
                    if (!((sel >> j) & 1)) ins4(v[j], j, m0, m1, m2, m3, i0, i1, i2, i3);
            }
        }
    }
    return sel;
}

// ---------------- kp1: layer-1 partials for alpha-h1 and beta-c1 (64 blocks) ----------------
__global__ __launch_bounds__(256) void kp1(const float* __restrict__ ba,
                                           const float* __restrict__ W1a,
                                           const float* __restrict__ bb,
                                           const float* __restrict__ W1b) {
    int t = threadIdx.x;
    int o = t & 127, sel = t >> 7;
    const float* W = sel ? W1b : W1a;
    const float* xv = sel ? bb : ba;
    int i0 = blockIdx.x * 16;
    float p = 0.f;
#pragma unroll
    for (int k = 0; k < 16; k++) p += xv[i0 + k] * W[(i0 + k) * 128 + o];
    d_p1[sel][blockIdx.x * 128 + o] = p;
}

// ---------------- kpa: reduce partials + alpha layers 2-3 (1 block x 1024) ----------------
__global__ __launch_bounds__(1024) void kpa(const float* __restrict__ b1a,
                                            const float* __restrict__ b1b,
                                            const float* __restrict__ W2a,
                                            const float* __restrict__ b2a,
                                            const float* __restrict__ W3a,
                                            const float* __restrict__ b3a,
                                            const float* __restrict__ ba) {
    __shared__ float h1[128];
    __shared__ float h2s[64];
    __shared__ float red[256];
    int t = threadIdx.x;
    if (t < 256) {
        int o = t & 127, sel = t >> 7;
        const float* p = d_p1[sel];
        float s = 0.f;
#pragma unroll 8
        for (int k = 0; k < 64; k++) s += p[k * 128 + o];
        if (sel == 0) h1[o] = leaky(b1a[o] + s);
        else d_c1[o] = b1b[o] + s;
    }
    __syncthreads();
    if (t < 256) {
        int o2 = t & 63, c2 = t >> 6;
        float q = 0.f;
#pragma unroll
        for (int k = 0; k < 32; k++) {
            int i = c2 * 32 + k;
            q += h1[i] * W2a[i * 64 + o2];
        }
        red[t] = q;
    }
    __syncthreads();
    if (t < 64)
        h2s[t] = leaky(b2a[t] + red[t] + red[64 + t] + red[128 + t] + red[192 + t]);
    __syncthreads();
    float s = 0.f;
#pragma unroll
    for (int i = 0; i < 64; i++) s += h2s[i] * W3a[i * 1024 + t];
    d_La[t] = s + b3a[t] + ba[t];
}

// ---------------- kmain: 512 threads, 16 rows/block, 2 CTAs/SM = 32 warps/SM ----------------
// Shared overlay (float offsets), total 17408 floats = 69632 B:
//   [0,1024)      h2t   | [1024,5120) W1b-slice | [5120,13312) W2b
//   [13312,14336) La_s  | [13312,15360) h1s (after alpha) | [15360,15872) ctx_s
//   [1024,17408)  lg (after layer 2)
constexpr int F_H2T = 0;
constexpr int F_W1  = 1024;
constexpr int F_W2  = 5120;
constexpr int F_LA  = 13312;
constexpr int F_H1  = 13312;
constexpr int F_CTX = 15360;
constexpr int F_LG  = 1024;
constexpr int SMEM_FLOATS = 17408;  // 69632 bytes

__global__ __launch_bounds__(512, 2) void kmain(
        const float* __restrict__ g_alpha, const float* __restrict__ g_beta,
        const float* __restrict__ Wc, const float* __restrict__ bc,
        const float* __restrict__ W1b, const float* __restrict__ W2b,
        const float* __restrict__ b2b, const float* __restrict__ W3b,
        const float* __restrict__ b3b, const float* __restrict__ baseline_b,
        float* __restrict__ out, int B) {
    extern __shared__ float sm[];
    float* h2t   = sm + F_H2T;
    float* w1s   = sm + F_W1;
    float* w2s   = sm + F_W2;
    float* La_s  = sm + F_LA;
    float* h1s   = sm + F_H1;
    float* ctx_s = sm + F_CTX;
    float* lg    = sm + F_LG;
    int t = threadIdx.x;
    int row0 = blockIdx.x * 16;
    if (row0 >= B) return;

    // vectorized fills (512 threads)
    if (t < 256) ((float4*)La_s)[t] = __ldg((const float4*)d_La + t);
#pragma unroll
    for (int x = 0; x < 2; x++)
        ((float4*)w1s)[x * 512 + t] = __ldg((const float4*)(W1b + 131072) + x * 512 + t);
#pragma unroll
    for (int x = 0; x < 4; x++)
        ((float4*)w2s)[x * 512 + t] = __ldg((const float4*)W2b + x * 512 + t);
    __syncthreads();

    int w = t >> 5, lane = t & 31;
    // ---- alpha: 1 row per warp (16 warps) ----
    {
        int row = row0 + w;
        if (row < B) {
            const float* g = g_alpha + (size_t)row * 1024;
            unsigned v[32];
#pragma unroll
            for (int j4 = 0; j4 < 8; j4++) {
                float4 lv = *(const float4*)(La_s + j4 * 128 + lane * 4);
                float4 gv = __ldg((const float4*)(g + j4 * 128 + lane * 4));
                v[j4 * 4 + 0] = f2ord(lv.x + gv.x);
                v[j4 * 4 + 1] = f2ord(lv.y + gv.y);
                v[j4 * 4 + 2] = f2ord(lv.z + gv.z);
                v[j4 * 4 + 3] = f2ord(lv.w + gv.w);
            }
            int gidx = 0;
            unsigned sel = warp_select32<true>(v, lane, &gidx);
            float* o = out + (size_t)row * 2048;
#pragma unroll
            for (int j4 = 0; j4 < 8; j4++) {
                float4 ov;
                ov.x = ((sel >> (j4 * 4 + 0)) & 1) ? 1.f : 0.f;
                ov.y = ((sel >> (j4 * 4 + 1)) & 1) ? 1.f : 0.f;
                ov.z = ((sel >> (j4 * 4 + 2)) & 1) ? 1.f : 0.f;
                ov.w = ((sel >> (j4 * 4 + 3)) & 1) ? 1.f : 0.f;
                *(float4*)(o + j4 * 128 + lane * 4) = ov;
            }
            // ctx = bc + sum of selected Wc rows
            float acc = __ldg(bc + lane);
#pragma unroll
            for (int k = 0; k < 32; k++) {
                int idx = __shfl_sync(FULLMASK, gidx, k);
                acc += __ldg(Wc + (size_t)idx * 32 + lane);
            }
            ctx_s[w * 32 + lane] = acc;
        } else {
            ctx_s[w * 32 + lane] = 0.f;
        }
    }
    __syncthreads();  // alpha done: La_s dead; h1s may overwrite it

    // ---- layer 1: row r = w, lane owns 4 contiguous outputs ----
    {
        float4 a = __ldg((const float4*)(d_c1 + lane * 4));
        const float* cr = ctx_s + w * 32;
#pragma unroll
        for (int i4 = 0; i4 < 32; i4 += 4) {
            float4 cv = *(const float4*)(cr + i4);
#pragma unroll
            for (int u = 0; u < 4; u++) {
                float c = (u == 0) ? cv.x : (u == 1) ? cv.y : (u == 2) ? cv.z : cv.w;
                float4 wv = *(const float4*)(w1s + (i4 + u) * 128 + lane * 4);
                a.x += c * wv.x; a.y += c * wv.y; a.z += c * wv.z; a.w += c * wv.w;
            }
        }
        *(float4*)(h1s + w * 128 + lane * 4) =
            make_float4(leaky(a.x), leaky(a.y), leaky(a.z), leaky(a.w));
    }
    __syncthreads();
    // ---- layer 2: row r = w, lane owns 2 contiguous outputs ----
    {
        float2 a = __ldg((const float2*)(b2b + lane * 2));
        const float* h1r = h1s + w * 128;
#pragma unroll 8
        for (int i4 = 0; i4 < 128; i4 += 4) {
            float4 hv = *(const float4*)(h1r + i4);
#pragma unroll
            for (int u = 0; u < 4; u++) {
                float h = (u == 0) ? hv.x : (u == 1) ? hv.y : (u == 2) ? hv.z : hv.w;
                float2 wv = *(const float2*)(w2s + (i4 + u) * 64 + lane * 2);
                a.x += h * wv.x; a.y += h * wv.y;
            }
        }
        h2t[(lane * 2 + 0) * 16 + w] = leaky(a.x);
        h2t[(lane * 2 + 1) * 16 + w] = leaky(a.y);
    }
    __syncthreads();  // h2t ready; rest of the pool dead -> lg
    // ---- layer 3: thread owns 2 outputs x 16 rows (f32x2 accumulators) ----
    {
        int o0 = t * 2;
        unsigned long long acc[16];
#pragma unroll
        for (int z = 0; z < 16; z++) acc[z] = 0ull;
#pragma unroll 4
        for (int i = 0; i < 64; i++) {
            float2 wv = __ldg((const float2*)(W3b + i * 1024 + o0));
            unsigned long long w0 = pack2(wv.x, wv.x);
            unsigned long long w1 = pack2(wv.y, wv.y);
            ulonglong2 p0 = *(const ulonglong2*)(h2t + i * 16);
            ulonglong2 p1 = *(const ulonglong2*)(h2t + i * 16 + 4);
            ulonglong2 p2 = *(const ulonglong2*)(h2t + i * 16 + 8);
            ulonglong2 p3 = *(const ulonglong2*)(h2t + i * 16 + 12);
            unsigned long long hh[8] = {p0.x, p0.y, p1.x, p1.y, p2.x, p2.y, p3.x, p3.y};
#pragma unroll
            for (int rp = 0; rp < 8; rp++) {
                acc[rp * 2 + 0] = fma2(w0, hh[rp], acc[rp * 2 + 0]);
                acc[rp * 2 + 1] = fma2(w1, hh[rp], acc[rp * 2 + 1]);
            }
        }
        float2 bv = __ldg((const float2*)(b3b + o0));
        float2 bb2 = __ldg((const float2*)(baseline_b + o0));
        float bq0 = bv.x + bb2.x, bq1 = bv.y + bb2.y;
#pragma unroll
        for (int rp = 0; rp < 8; rp++) {
            float lo0, hi0, lo1, hi1;
            unpack2(acc[rp * 2 + 0], lo0, hi0);
            unpack2(acc[rp * 2 + 1], lo1, hi1);
            *(float2*)(lg + (rp * 2) * 1024 + o0) = make_float2(lo0 + bq0, lo1 + bq1);
            *(float2*)(lg + (rp * 2 + 1) * 1024 + o0) = make_float2(hi0 + bq0, hi1 + bq1);
        }
    }
    __syncthreads();
    // ---- beta selection: 1 row per warp ----
    {
        int row = row0 + w;
        if (row < B) {
            const float* g = g_beta + (size_t)row * 1024;
            unsigned v[32];
#pragma unroll
            for (int j4 = 0; j4 < 8; j4++) {
                float4 lv = *(const float4*)(lg + w * 1024 + j4 * 128 + lane * 4);
                float4 gv = __ldg((const float4*)(g + j4 * 128 + lane * 4));
                v[j4 * 4 + 0] = f2ord(lv.x + gv.x);
                v[j4 * 4 + 1] = f2ord(lv.y + gv.y);
                v[j4 * 4 + 2] = f2ord(lv.z + gv.z);
                v[j4 * 4 + 3] = f2ord(lv.w + gv.w);
            }
            int dummy;
            unsigned sel = warp_select32<false>(v, lane, &dummy);
            float* o = out + (size_t)row * 2048 + 1024;
#pragma unroll
            for (int j4 = 0; j4 < 8; j4++) {
                float4 ov;
                ov.x = ((sel >> (j4 * 4 + 0)) & 1) ? 1.f : 0.f;
                ov.y = ((sel >> (j4 * 4 + 1)) & 1) ? 1.f : 0.f;
                ov.z = ((sel >> (j4 * 4 + 2)) & 1) ? 1.f : 0.f;
                ov.w = ((sel >> (j4 * 4 + 3)) & 1) ? 1.f : 0.f;
                *(float4*)(o + j4 * 128 + lane * 4) = ov;
            }
        }
    }
}

// ---------------- launcher ----------------
extern "C" void kernel_launch(void* const* d_in, const int* in_sizes, int n_in,
                              void* d_out, int out_size) {
    const float* baseline_a = (const float*)d_in[0];
    const float* W1a = (const float*)d_in[1];
    const float* b1a = (const float*)d_in[2];
    const float* W2a = (const float*)d_in[3];
    const float* b2a = (const float*)d_in[4];
    const float* W3a = (const float*)d_in[5];
    const float* b3a = (const float*)d_in[6];
    const float* baseline_b = (const float*)d_in[7];
    const float* Wc  = (const float*)d_in[8];
    const float* bc  = (const float*)d_in[9];
    const float* W1b = (const float*)d_in[10];
    const float* b1b = (const float*)d_in[11];
    const float* W2b = (const float*)d_in[12];
    const float* b2b = (const float*)d_in[13];
    const float* W3b = (const float*)d_in[14];
    const float* b3b = (const float*)d_in[15];
    const float* g_alpha = (const float*)d_in[16];
    const float* g_beta  = (const float*)d_in[17];
    float* out = (float*)d_out;

    int B = in_sizes[16] / 1024;
    if (B <= 0) return;

    cudaFuncSetAttribute(kmain, cudaFuncAttributeMaxDynamicSharedMemorySize,
                         SMEM_FLOATS * sizeof(float));

    kp1<<<64, 256>>>(baseline_a, W1a, baseline_b, W1b);
    kpa<<<1, 1024>>>(b1a, b1b, W2a, b2a, W3a, b3a, baseline_a);
    kmain<<<(B + 15) / 16, 512, SMEM_FLOATS * sizeof(float)>>>(
        g_alpha, g_beta, Wc, bc, W1b, W2b, b2b, W3b, b3b, baseline_b, out, B);
}